// round 4
// baseline (speedup 1.0000x reference)
#include <cuda_runtime.h>
#include <stdint.h>

// Problem constants (fixed shapes)
#define N_A   500000
#define N_B   500000
#define NE    1000000
#define HID   64
#define NOUT  32

// ---------------- scratch (device globals: allocation-free) ----------------
__device__ float g_agg_ab[N_B];            // layer-1 scalar aggregates
__device__ float g_agg_ba[N_A];
__device__ float g_agg_aa[N_A];
__device__ float g_ta_ab[(size_t)N_A * NOUT];   // ha @ Wrel2[0]  (src-transform for a->b)
__device__ float g_ta_aa[(size_t)N_A * NOUT];   // ha @ Wrel2[2]  (src-transform for a->a)
__device__ float g_tb_ba[(size_t)N_B * NOUT];   // hb @ Wrel2[1]  (src-transform for b->a)
__device__ int   g_is64;                   // edge-index dtype flag

// ---------------- dtype probe ----------------
// int64 little-endian indices < 2^31 => every odd 32-bit word is 0.
__global__ void probe_kernel(const unsigned* __restrict__ ei) {
    __shared__ unsigned s;
    if (threadIdx.x == 0) s = 0u;
    __syncthreads();
    unsigned v = 0u;
    for (int i = threadIdx.x; i < 2048; i += blockDim.x) v |= ei[2 * i + 1];
    atomicOr(&s, v);
    __syncthreads();
    if (threadIdx.x == 0) g_is64 = (s == 0u) ? 1 : 0;
}

__device__ __forceinline__ int ld_idx(const void* __restrict__ ei, int row, int i, int is64) {
    if (is64) return (int)((const unsigned*)ei)[(((size_t)row * NE) + i) * 2];   // low word
    return ((const int*)ei)[((size_t)row * NE) + i];
}

// ---------------- zero the scalar aggregates (needed every replay) ----------------
__global__ void zero_aggs() {
    int gid = blockIdx.x * blockDim.x + threadIdx.x;
    if (gid < N_B) g_agg_ab[gid] = 0.f;
    if (gid < N_A) { g_agg_ba[gid] = 0.f; g_agg_aa[gid] = 0.f; }
}

// ---------------- layer-1 edge kernel: scalar scatter-add ----------------
__global__ void l1_edge(const void* __restrict__ ei_ab,
                        const void* __restrict__ ei_ba,
                        const void* __restrict__ ei_aa,
                        const float* __restrict__ xa,
                        const float* __restrict__ xb) {
    int gid = blockIdx.x * blockDim.x + threadIdx.x;
    if (gid >= 3 * NE) return;
    int is64 = g_is64;
    int t = gid / NE;
    int e = gid - t * NE;
    if (t == 0) {
        int s = ld_idx(ei_ab, 0, e, is64), d = ld_idx(ei_ab, 1, e, is64);
        atomicAdd(&g_agg_ab[d], xa[s]);                 // a -> b gathers x_a
    } else if (t == 1) {
        int s = ld_idx(ei_ba, 0, e, is64), d = ld_idx(ei_ba, 1, e, is64);
        atomicAdd(&g_agg_ba[d], xb[s]);                 // b -> a gathers x_b
    } else {
        int s = ld_idx(ei_aa, 0, e, is64), d = ld_idx(ei_aa, 1, e, is64);
        atomicAdd(&g_agg_aa[d], xa[s]);                 // a -> a gathers x_a
    }
}

// ---------------- fused node matvec pass ----------------
// h[k] = relu(s1*u[k] + s2*v[k] + s3*w[k] + c[k]);  dst[j] = bias[j] + sum_k h[k]*W[k][j]
__device__ __forceinline__ void node_pass(
    const float* __restrict__ sW,      // [HID*NOUT] in shared
    const float* __restrict__ su, const float* __restrict__ sv,
    const float* __restrict__ sw_, const float* __restrict__ sc,
    float s1, float s2, float s3,
    const float* __restrict__ sbias,   // nullptr => zero init
    float* __restrict__ dst)
{
    float acc[NOUT];
#pragma unroll
    for (int j = 0; j < NOUT; j++) acc[j] = sbias ? sbias[j] : 0.f;

#pragma unroll 1
    for (int k4 = 0; k4 < HID / 4; k4++) {
        float4 u  = ((const float4*)su)[k4];
        float4 v  = ((const float4*)sv)[k4];
        float4 w  = ((const float4*)sw_)[k4];
        float4 c  = ((const float4*)sc)[k4];
        float hk[4];
        hk[0] = fmaxf(fmaf(s1, u.x, fmaf(s2, v.x, fmaf(s3, w.x, c.x))), 0.f);
        hk[1] = fmaxf(fmaf(s1, u.y, fmaf(s2, v.y, fmaf(s3, w.y, c.y))), 0.f);
        hk[2] = fmaxf(fmaf(s1, u.z, fmaf(s2, v.z, fmaf(s3, w.z, c.z))), 0.f);
        hk[3] = fmaxf(fmaf(s1, u.w, fmaf(s2, v.w, fmaf(s3, w.w, c.w))), 0.f);
#pragma unroll
        for (int kk = 0; kk < 4; kk++) {
            int k = 4 * k4 + kk;
            const float4* wr = (const float4*)(sW + k * NOUT);
            float h = hk[kk];
#pragma unroll
            for (int j4 = 0; j4 < NOUT / 4; j4++) {
                float4 ww = wr[j4];
                acc[4 * j4 + 0] = fmaf(h, ww.x, acc[4 * j4 + 0]);
                acc[4 * j4 + 1] = fmaf(h, ww.y, acc[4 * j4 + 1]);
                acc[4 * j4 + 2] = fmaf(h, ww.z, acc[4 * j4 + 2]);
                acc[4 * j4 + 3] = fmaf(h, ww.w, acc[4 * j4 + 3]);
            }
        }
    }
    float4* o = (float4*)dst;
#pragma unroll
    for (int j4 = 0; j4 < NOUT / 4; j4++)
        o[j4] = make_float4(acc[4 * j4], acc[4 * j4 + 1], acc[4 * j4 + 2], acc[4 * j4 + 3]);
}

// ---------------- node kernel for 'a' nodes ----------------
// ha = relu(agg_ba*Wr1[1] + agg_aa*Wr1[2] + x_a*(Wo1[1]+Wo1[2]) + b1[1]+b1[2])
// writes: g_ta_ab = ha@Wr2[0], g_ta_aa = ha@Wr2[2], out[i] = ha@(Wo2[1]+Wo2[2]) + b2[1]+b2[2]
__global__ void node_a(const float* __restrict__ xa,
                       const float* __restrict__ Wr1, const float* __restrict__ Wo1,
                       const float* __restrict__ b1,
                       const float* __restrict__ Wr2, const float* __restrict__ Wo2,
                       const float* __restrict__ b2,
                       float* __restrict__ out) {
    __shared__ __align__(16) float su[HID], sv[HID], sw_[HID], sc[HID];
    __shared__ __align__(16) float sWab[HID * NOUT], sWaa[HID * NOUT], sWroot[HID * NOUT];
    __shared__ __align__(16) float sbias[NOUT];
    int tid = threadIdx.x;
    for (int i = tid; i < HID; i += blockDim.x) {
        su[i]  = Wr1[1 * HID + i];
        sv[i]  = Wr1[2 * HID + i];
        sw_[i] = Wo1[1 * HID + i] + Wo1[2 * HID + i];
        sc[i]  = b1[1 * HID + i] + b1[2 * HID + i];
    }
    for (int i = tid; i < HID * NOUT; i += blockDim.x) {
        sWab[i]   = Wr2[0 * HID * NOUT + i];
        sWaa[i]   = Wr2[2 * HID * NOUT + i];
        sWroot[i] = Wo2[1 * HID * NOUT + i] + Wo2[2 * HID * NOUT + i];
    }
    for (int i = tid; i < NOUT; i += blockDim.x) sbias[i] = b2[1 * NOUT + i] + b2[2 * NOUT + i];
    __syncthreads();

    int n = blockIdx.x * blockDim.x + tid;
    if (n >= N_A) return;
    float s1 = g_agg_ba[n];
    float s2 = g_agg_aa[n];
    float s3 = xa[n];

    node_pass(sWab,   su, sv, sw_, sc, s1, s2, s3, nullptr, g_ta_ab + (size_t)n * NOUT);
    node_pass(sWaa,   su, sv, sw_, sc, s1, s2, s3, nullptr, g_ta_aa + (size_t)n * NOUT);
    node_pass(sWroot, su, sv, sw_, sc, s1, s2, s3, sbias,   out + (size_t)n * NOUT);
}

// ---------------- node kernel for 'b' nodes ----------------
// hb = relu(agg_ab*Wr1[0] + x_b*Wo1[0] + b1[0])
// writes: g_tb_ba = hb@Wr2[1], out[N_A+i] = hb@Wo2[0] + b2[0]
__global__ void node_b(const float* __restrict__ xb,
                       const float* __restrict__ Wr1, const float* __restrict__ Wo1,
                       const float* __restrict__ b1,
                       const float* __restrict__ Wr2, const float* __restrict__ Wo2,
                       const float* __restrict__ b2,
                       float* __restrict__ out) {
    __shared__ __align__(16) float su[HID], sw_[HID], sc[HID];
    __shared__ __align__(16) float sWba[HID * NOUT], sWroot[HID * NOUT];
    __shared__ __align__(16) float sbias[NOUT];
    int tid = threadIdx.x;
    for (int i = tid; i < HID; i += blockDim.x) {
        su[i]  = Wr1[0 * HID + i];
        sw_[i] = Wo1[0 * HID + i];
        sc[i]  = b1[0 * HID + i];
    }
    for (int i = tid; i < HID * NOUT; i += blockDim.x) {
        sWba[i]   = Wr2[1 * HID * NOUT + i];
        sWroot[i] = Wo2[0 * HID * NOUT + i];
    }
    for (int i = tid; i < NOUT; i += blockDim.x) sbias[i] = b2[0 * NOUT + i];
    __syncthreads();

    int n = blockIdx.x * blockDim.x + tid;
    if (n >= N_B) return;
    float s1 = g_agg_ab[n];
    float s3 = xb[n];

    // s2 term unused: pass 0 with sv aliased to su
    node_pass(sWba,   su, su, sw_, sc, s1, 0.f, s3, nullptr, g_tb_ba + (size_t)n * NOUT);
    node_pass(sWroot, su, su, sw_, sc, s1, 0.f, s3, sbias,   out + (size_t)(N_A + n) * NOUT);
}

// ---------------- layer-2 edge kernel: 32-wide row scatter via red.v4 ----------------
// one thread per (edge, float4-quadrant): 3*NE*8 threads
__global__ void l2_edge(const void* __restrict__ ei_ab,
                        const void* __restrict__ ei_ba,
                        const void* __restrict__ ei_aa,
                        float* __restrict__ out) {
    long long gid = (long long)blockIdx.x * blockDim.x + threadIdx.x;
    if (gid >= 3LL * NE * 8) return;
    int is64 = g_is64;
    int t = (int)(gid / (NE * 8LL));
    long long r = gid - (long long)t * (NE * 8LL);
    int e = (int)(r >> 3);
    int q = (int)(r & 7);

    const void* ei = (t == 0) ? ei_ab : ((t == 1) ? ei_ba : ei_aa);
    int s = ld_idx(ei, 0, e, is64);
    int d = ld_idx(ei, 1, e, is64);

    const float* tsrc = (t == 0) ? g_ta_ab : ((t == 1) ? g_tb_ba : g_ta_aa);
    size_t drow = (t == 0) ? (size_t)(N_A + d) : (size_t)d;   // ab edges land in b-rows

    float4 v = *(const float4*)(tsrc + (size_t)s * NOUT + q * 4);
    float* p = out + drow * NOUT + q * 4;
    asm volatile("red.global.add.v4.f32 [%0], {%1, %2, %3, %4};"
                 :: "l"(p), "f"(v.x), "f"(v.y), "f"(v.z), "f"(v.w)
                 : "memory");
}

// ---------------- launch ----------------
extern "C" void kernel_launch(void* const* d_in, const int* in_sizes, int n_in,
                              void* d_out, int out_size) {
    const float* x_a   = (const float*)d_in[0];
    const float* x_b   = (const float*)d_in[1];
    const void*  ei_ab = d_in[2];
    const void*  ei_ba = d_in[3];
    const void*  ei_aa = d_in[4];
    const float* Wr1   = (const float*)d_in[5];
    const float* Wo1   = (const float*)d_in[6];
    const float* b1    = (const float*)d_in[7];
    const float* Wr2   = (const float*)d_in[8];
    const float* Wo2   = (const float*)d_in[9];
    const float* b2    = (const float*)d_in[10];
    float* out = (float*)d_out;

    probe_kernel<<<1, 256>>>((const unsigned*)ei_ab);

    zero_aggs<<<(N_A + 255) / 256, 256>>>();

    l1_edge<<<(3 * NE + 255) / 256, 256>>>(ei_ab, ei_ba, ei_aa, x_a, x_b);

    node_a<<<(N_A + 255) / 256, 256>>>(x_a, Wr1, Wo1, b1, Wr2, Wo2, b2, out);
    node_b<<<(N_B + 255) / 256, 256>>>(x_b, Wr1, Wo1, b1, Wr2, Wo2, b2, out);

    long long l2_items = 3LL * NE * 8;
    int l2_blocks = (int)((l2_items + 255) / 256);
    l2_edge<<<l2_blocks, 256>>>(ei_ab, ei_ba, ei_aa, out);
}

// round 5
// speedup vs baseline: 1.4006x; 1.4006x over previous
#include <cuda_runtime.h>
#include <stdint.h>

// Problem constants (fixed shapes)
#define N_A   500000
#define N_B   500000
#define NE    1000000
#define HID   64
#define NOUT  32

// ---------------- scratch (device globals: allocation-free) ----------------
__device__ float g_agg_ab[N_B];            // layer-1 scalar aggregates
__device__ float g_agg_ba[N_A];
__device__ float g_agg_aa[N_A];
__device__ float g_ta_ab[(size_t)N_A * NOUT];   // ha @ Wrel2[0]  (src-transform for a->b)
__device__ float g_ta_aa[(size_t)N_A * NOUT];   // ha @ Wrel2[2]  (src-transform for a->a)
__device__ float g_tb_ba[(size_t)N_B * NOUT];   // hb @ Wrel2[1]  (src-transform for b->a)
__device__ int   g_is64;                   // edge-index dtype flag

// ---------------- dtype probe ----------------
// int64 little-endian indices < 2^31 => every odd 32-bit word is 0.
__global__ void probe_kernel(const unsigned* __restrict__ ei) {
    __shared__ unsigned s;
    if (threadIdx.x == 0) s = 0u;
    __syncthreads();
    unsigned v = 0u;
    for (int i = threadIdx.x; i < 2048; i += blockDim.x) v |= ei[2 * i + 1];
    atomicOr(&s, v);
    __syncthreads();
    if (threadIdx.x == 0) g_is64 = (s == 0u) ? 1 : 0;
}

__device__ __forceinline__ int ld_idx(const void* __restrict__ ei, int row, int i, int is64) {
    if (is64) return (int)((const unsigned*)ei)[(((size_t)row * NE) + i) * 2];   // low word
    return ((const int*)ei)[((size_t)row * NE) + i];
}

// ---------------- zero the scalar aggregates (needed every replay) ----------------
__global__ void zero_aggs() {
    int gid = blockIdx.x * blockDim.x + threadIdx.x;
    if (gid < N_B) g_agg_ab[gid] = 0.f;
    if (gid < N_A) { g_agg_ba[gid] = 0.f; g_agg_aa[gid] = 0.f; }
}

// ---------------- layer-1 edge kernel: scalar scatter-add ----------------
__global__ void l1_edge(const void* __restrict__ ei_ab,
                        const void* __restrict__ ei_ba,
                        const void* __restrict__ ei_aa,
                        const float* __restrict__ xa,
                        const float* __restrict__ xb) {
    int gid = blockIdx.x * blockDim.x + threadIdx.x;
    if (gid >= 3 * NE) return;
    int is64 = g_is64;
    int t = gid / NE;
    int e = gid - t * NE;
    if (t == 0) {
        int s = ld_idx(ei_ab, 0, e, is64), d = ld_idx(ei_ab, 1, e, is64);
        atomicAdd(&g_agg_ab[d], xa[s]);                 // a -> b gathers x_a
    } else if (t == 1) {
        int s = ld_idx(ei_ba, 0, e, is64), d = ld_idx(ei_ba, 1, e, is64);
        atomicAdd(&g_agg_ba[d], xb[s]);                 // b -> a gathers x_b
    } else {
        int s = ld_idx(ei_aa, 0, e, is64), d = ld_idx(ei_aa, 1, e, is64);
        atomicAdd(&g_agg_aa[d], xa[s]);                 // a -> a gathers x_a
    }
}

// ---------------- packed f32x2 helpers ----------------
__device__ __forceinline__ unsigned long long pack2(float h) {
    unsigned long long r;
    asm("mov.b64 %0, {%1, %1};" : "=l"(r) : "f"(h));
    return r;
}
#define FMA2(acc, w, h) \
    asm("fma.rn.f32x2 %0, %1, %2, %0;" : "+l"(acc) : "l"(w), "l"(h))

// ================= node kernel for 'a' nodes (fused 96-col sweep) =================
// h[k] = relu(s1*u + s2*v + s3*w + c), single pass over k with concatenated
// weights [64][96] = Wrel2[0] | Wrel2[2] | (Wroot2[1]+Wroot2[2]).
__global__ void __launch_bounds__(128)
node_a(const float* __restrict__ xa,
       const float* __restrict__ Wr1, const float* __restrict__ Wo1,
       const float* __restrict__ b1,
       const float* __restrict__ Wr2, const float* __restrict__ Wo2,
       const float* __restrict__ b2,
       float* __restrict__ out) {
    __shared__ __align__(16) float  sW[HID * 96];   // 24 KB concatenated weights
    __shared__ __align__(16) float4 sH[HID];        // {u, v, w, c} per k
    __shared__ __align__(16) float  sbias[NOUT];

    int tid = threadIdx.x;
    for (int idx = tid; idx < HID * 96; idx += blockDim.x) {
        int k = idx / 96, j = idx - k * 96;
        float v;
        if (j < 32)       v = Wr2[0 * HID * NOUT + k * NOUT + j];
        else if (j < 64)  v = Wr2[2 * HID * NOUT + k * NOUT + (j - 32)];
        else              v = Wo2[1 * HID * NOUT + k * NOUT + (j - 64)]
                            + Wo2[2 * HID * NOUT + k * NOUT + (j - 64)];
        sW[idx] = v;
    }
    for (int k = tid; k < HID; k += blockDim.x) {
        sH[k] = make_float4(Wr1[1 * HID + k],
                            Wr1[2 * HID + k],
                            Wo1[1 * HID + k] + Wo1[2 * HID + k],
                            b1[1 * HID + k] + b1[2 * HID + k]);
    }
    for (int j = tid; j < NOUT; j += blockDim.x)
        sbias[j] = b2[1 * NOUT + j] + b2[2 * NOUT + j];
    __syncthreads();

    int n = blockIdx.x * blockDim.x + tid;
    if (n >= N_A) return;
    float s1 = g_agg_ba[n];
    float s2 = g_agg_aa[n];
    float s3 = xa[n];

    unsigned long long acc[48];
#pragma unroll
    for (int i = 0; i < 32; i++) acc[i] = 0ULL;
    {
        const unsigned long long* pb = (const unsigned long long*)sbias;
#pragma unroll
        for (int i = 0; i < 16; i++) acc[32 + i] = pb[i];
    }

#pragma unroll 1
    for (int k = 0; k < HID; k++) {
        float4 q = sH[k];
        float h = fmaxf(fmaf(s1, q.x, fmaf(s2, q.y, fmaf(s3, q.z, q.w))), 0.f);
        unsigned long long hh = pack2(h);
        const ulonglong2* wrow = (const ulonglong2*)(sW + k * 96);
#pragma unroll
        for (int i = 0; i < 24; i++) {
            ulonglong2 wv = wrow[i];
            FMA2(acc[2 * i],     wv.x, hh);
            FMA2(acc[2 * i + 1], wv.y, hh);
        }
    }

    // stores: cols [0,32) -> g_ta_ab, [32,64) -> g_ta_aa, [64,96) -> out (+bias already in acc)
    {
        ulonglong2* o0 = (ulonglong2*)(g_ta_ab + (size_t)n * NOUT);
        ulonglong2* o1 = (ulonglong2*)(g_ta_aa + (size_t)n * NOUT);
        ulonglong2* o2 = (ulonglong2*)(out + (size_t)n * NOUT);
#pragma unroll
        for (int i = 0; i < 8; i++) {
            o0[i] = make_ulonglong2(acc[2 * i],      acc[2 * i + 1]);
            o1[i] = make_ulonglong2(acc[16 + 2 * i], acc[16 + 2 * i + 1]);
            o2[i] = make_ulonglong2(acc[32 + 2 * i], acc[32 + 2 * i + 1]);
        }
    }
}

// ================= node kernel for 'b' nodes (fused 64-col sweep) =================
// h[k] = relu(s1*u + s3*w + c); weights [64][64] = Wrel2[1] | Wroot2[0].
__global__ void __launch_bounds__(128)
node_b(const float* __restrict__ xb,
       const float* __restrict__ Wr1, const float* __restrict__ Wo1,
       const float* __restrict__ b1,
       const float* __restrict__ Wr2, const float* __restrict__ Wo2,
       const float* __restrict__ b2,
       float* __restrict__ out) {
    __shared__ __align__(16) float  sW[HID * 64];   // 16 KB
    __shared__ __align__(16) float4 sH[HID];        // {u, w, c, 0}
    __shared__ __align__(16) float  sbias[NOUT];

    int tid = threadIdx.x;
    for (int idx = tid; idx < HID * 64; idx += blockDim.x) {
        int k = idx / 64, j = idx - k * 64;
        float v;
        if (j < 32) v = Wr2[1 * HID * NOUT + k * NOUT + j];
        else        v = Wo2[0 * HID * NOUT + k * NOUT + (j - 32)];
        sW[idx] = v;
    }
    for (int k = tid; k < HID; k += blockDim.x) {
        sH[k] = make_float4(Wr1[0 * HID + k],
                            Wo1[0 * HID + k],
                            b1[0 * HID + k],
                            0.f);
    }
    for (int j = tid; j < NOUT; j += blockDim.x) sbias[j] = b2[0 * NOUT + j];
    __syncthreads();

    int n = blockIdx.x * blockDim.x + tid;
    if (n >= N_B) return;
    float s1 = g_agg_ab[n];
    float s3 = xb[n];

    unsigned long long acc[32];
#pragma unroll
    for (int i = 0; i < 16; i++) acc[i] = 0ULL;
    {
        const unsigned long long* pb = (const unsigned long long*)sbias;
#pragma unroll
        for (int i = 0; i < 16; i++) acc[16 + i] = pb[i];
    }

#pragma unroll 1
    for (int k = 0; k < HID; k++) {
        float4 q = sH[k];
        float h = fmaxf(fmaf(s1, q.x, fmaf(s3, q.y, q.z)), 0.f);
        unsigned long long hh = pack2(h);
        const ulonglong2* wrow = (const ulonglong2*)(sW + k * 64);
#pragma unroll
        for (int i = 0; i < 16; i++) {
            ulonglong2 wv = wrow[i];
            FMA2(acc[2 * i],     wv.x, hh);
            FMA2(acc[2 * i + 1], wv.y, hh);
        }
    }

    {
        ulonglong2* o0 = (ulonglong2*)(g_tb_ba + (size_t)n * NOUT);
        ulonglong2* o1 = (ulonglong2*)(out + (size_t)(N_A + n) * NOUT);
#pragma unroll
        for (int i = 0; i < 8; i++) {
            o0[i] = make_ulonglong2(acc[2 * i],      acc[2 * i + 1]);
            o1[i] = make_ulonglong2(acc[16 + 2 * i], acc[16 + 2 * i + 1]);
        }
    }
}

// ---------------- layer-2 edge kernel: 32-wide row scatter via red.v4 ----------------
// one thread per (edge, float4-quadrant): 3*NE*8 threads
__global__ void l2_edge(const void* __restrict__ ei_ab,
                        const void* __restrict__ ei_ba,
                        const void* __restrict__ ei_aa,
                        float* __restrict__ out) {
    long long gid = (long long)blockIdx.x * blockDim.x + threadIdx.x;
    if (gid >= 3LL * NE * 8) return;
    int is64 = g_is64;
    int t = (int)(gid / (NE * 8LL));
    long long r = gid - (long long)t * (NE * 8LL);
    int e = (int)(r >> 3);
    int q = (int)(r & 7);

    const void* ei = (t == 0) ? ei_ab : ((t == 1) ? ei_ba : ei_aa);
    int s = ld_idx(ei, 0, e, is64);
    int d = ld_idx(ei, 1, e, is64);

    const float* tsrc = (t == 0) ? g_ta_ab : ((t == 1) ? g_tb_ba : g_ta_aa);
    size_t drow = (t == 0) ? (size_t)(N_A + d) : (size_t)d;   // ab edges land in b-rows

    float4 v = *(const float4*)(tsrc + (size_t)s * NOUT + q * 4);
    float* p = out + drow * NOUT + q * 4;
    asm volatile("red.global.add.v4.f32 [%0], {%1, %2, %3, %4};"
                 :: "l"(p), "f"(v.x), "f"(v.y), "f"(v.z), "f"(v.w)
                 : "memory");
}

// ---------------- launch ----------------
extern "C" void kernel_launch(void* const* d_in, const int* in_sizes, int n_in,
                              void* d_out, int out_size) {
    const float* x_a   = (const float*)d_in[0];
    const float* x_b   = (const float*)d_in[1];
    const void*  ei_ab = d_in[2];
    const void*  ei_ba = d_in[3];
    const void*  ei_aa = d_in[4];
    const float* Wr1   = (const float*)d_in[5];
    const float* Wo1   = (const float*)d_in[6];
    const float* b1    = (const float*)d_in[7];
    const float* Wr2   = (const float*)d_in[8];
    const float* Wo2   = (const float*)d_in[9];
    const float* b2    = (const float*)d_in[10];
    float* out = (float*)d_out;

    probe_kernel<<<1, 256>>>((const unsigned*)ei_ab);

    zero_aggs<<<(N_A + 255) / 256, 256>>>();

    l1_edge<<<(3 * NE + 255) / 256, 256>>>(ei_ab, ei_ba, ei_aa, x_a, x_b);

    node_a<<<(N_A + 127) / 128, 128>>>(x_a, Wr1, Wo1, b1, Wr2, Wo2, b2, out);
    node_b<<<(N_B + 127) / 128, 128>>>(x_b, Wr1, Wo1, b1, Wr2, Wo2, b2, out);

    long long l2_items = 3LL * NE * 8;
    int l2_blocks = (int)((l2_items + 255) / 256);
    l2_edge<<<l2_blocks, 256>>>(ei_ab, ei_ba, ei_aa, out);
}